// round 8
// baseline (speedup 1.0000x reference)
#include <cuda_runtime.h>
#include <cstdint>

// Problem constants
#define S_LEN 2048
#define EMB   1024
#define HEADS 16
#define DH    64
#define BATCH 2

// Scratch (no allocations allowed)
__device__ float g_qkv[(size_t)BATCH * S_LEN * 3 * EMB];   // [B,S,3E]
__device__ float g_ctx[(size_t)BATCH * S_LEN * EMB];       // [B,S,E] (tf32-rounded)
__device__ float g_xr [(size_t)BATCH * S_LEN * EMB];       // rounded x
__device__ float g_wir[(size_t)3 * EMB * EMB];             // rounded in_proj_w
__device__ float g_wor[(size_t)EMB * EMB];                 // rounded out_proj_w

// ===========================================================================
// Helpers
// ===========================================================================
__device__ __forceinline__ uint32_t smem_u32(const void* p) {
    uint32_t a;
    asm("{ .reg .u64 t; cvta.to.shared.u64 t, %1; cvt.u32.u64 %0, t; }"
        : "=r"(a) : "l"(p));
    return a;
}

__device__ __forceinline__ void cp_async16(uint32_t dst, const void* src) {
    asm volatile("cp.async.cg.shared.global [%0], [%1], 16;"
                 :: "r"(dst), "l"(src));
}
#define CP_COMMIT() asm volatile("cp.async.commit_group;")
#define CP_WAIT1()  asm volatile("cp.async.wait_group 1;")
#define CP_WAIT0()  asm volatile("cp.async.wait_group 0;")

__device__ __forceinline__ uint32_t f2tf32(float f) {
    uint32_t r;
    asm("cvt.rna.tf32.f32 %0, %1;" : "=r"(r) : "f"(f));
    return r;
}
__device__ __forceinline__ float rnd_tf32(float f) {
    return __uint_as_float(f2tf32(f));
}

// bf16 round-to-nearest-even "hi" part of an fp32 (exact bf16 value as fp32)
__device__ __forceinline__ float bf16_hi(float x) {
    uint32_t xb = __float_as_uint(x);
    uint32_t hb = (xb + 0x7fffu + ((xb >> 16) & 1u)) & 0xffff0000u;
    return __uint_as_float(hb);
}
// Pack two fp32 -> bf16x2 register: e0 -> low half (lower k index), e1 -> high
__device__ __forceinline__ uint32_t pack2_bf16(float e0, float e1) {
    uint32_t r;
    asm("cvt.rn.bf16x2.f32 %0, %1, %2;" : "=r"(r) : "f"(e1), "f"(e0));
    return r;
}

// mma.sync m16n8k8 tf32: D += A*B, fp32 accumulate
__device__ __forceinline__ void mma_tf32(
    float* c, const uint32_t* a, const uint32_t* b)
{
    asm volatile(
        "mma.sync.aligned.m16n8k8.row.col.f32.tf32.tf32.f32 "
        "{%0,%1,%2,%3}, {%4,%5,%6,%7}, {%8,%9}, {%0,%1,%2,%3};"
        : "+f"(c[0]), "+f"(c[1]), "+f"(c[2]), "+f"(c[3])
        : "r"(a[0]), "r"(a[1]), "r"(a[2]), "r"(a[3]), "r"(b[0]), "r"(b[1]));
}

// mma.sync m16n8k16 bf16: D += A*B, fp32 accumulate
__device__ __forceinline__ void mma_bf16(
    float* c, const uint32_t* a, const uint32_t* b)
{
    asm volatile(
        "mma.sync.aligned.m16n8k16.row.col.f32.bf16.bf16.f32 "
        "{%0,%1,%2,%3}, {%4,%5,%6,%7}, {%8,%9}, {%0,%1,%2,%3};"
        : "+f"(c[0]), "+f"(c[1]), "+f"(c[2]), "+f"(c[3])
        : "r"(a[0]), "r"(a[1]), "r"(a[2]), "r"(a[3]), "r"(b[0]), "r"(b[1]));
}

// ===========================================================================
// Elementwise tf32 pre-rounding (RNA). Idempotent; feeds GEMMs raw bits.
// ===========================================================================
__global__ __launch_bounds__(256) void round_tf32_kernel(
    const float4* __restrict__ src, float4* __restrict__ dst, int n4)
{
    for (int i = blockIdx.x * 256 + threadIdx.x; i < n4; i += gridDim.x * 256) {
        float4 v = src[i];
        v.x = rnd_tf32(v.x); v.y = rnd_tf32(v.y);
        v.z = rnd_tf32(v.z); v.w = rnd_tf32(v.w);
        dst[i] = v;
    }
}

// ===========================================================================
// tf32 tensor-core GEMM on PRE-ROUNDED inputs (unchanged from round 7):
//   C[M,N] = A[M,K] @ B[N,K]^T + bias[N]
// ===========================================================================
#define PAD     36
#define TILE_F  (128 * PAD)
#define BUF_F   (2 * TILE_F)
#define GM_SMEM (2 * BUF_F * 4)

__global__ __launch_bounds__(256, 2) void gemm_mma(
    const float* __restrict__ A, const float* __restrict__ B,
    const float* __restrict__ bias, float* __restrict__ C,
    int M, int N, int K)
{
    extern __shared__ float smem[];
    const int tid  = threadIdx.x;
    const int wid  = tid >> 5;
    const int lane = tid & 31;
    const int wm   = wid >> 2;
    const int wn   = wid & 3;
    const int g    = lane >> 2;
    const int tig  = lane & 3;
    const int bm   = blockIdx.y * 128;
    const int bn   = blockIdx.x * 128;

    float acc[4][4][4];
    #pragma unroll
    for (int mt = 0; mt < 4; mt++)
        #pragma unroll
        for (int nt = 0; nt < 4; nt++)
            #pragma unroll
            for (int i = 0; i < 4; i++)
                acc[mt][nt][i] = 0.0f;

    auto fill = [&](int buf, int kc) {
        const int k0 = kc << 5;
        const uint32_t sA = smem_u32(smem + buf * BUF_F);
        const uint32_t sB = sA + TILE_F * 4;
        #pragma unroll
        for (int i = 0; i < 4; i++) {
            const int id = tid + (i << 8);
            const int r  = id >> 3;
            const int c  = id & 7;
            const uint32_t so = (uint32_t)(r * PAD + c * 4) * 4;
            cp_async16(sA + so, A + (size_t)(bm + r) * K + k0 + c * 4);
            cp_async16(sB + so, B + (size_t)(bn + r) * K + k0 + c * 4);
        }
        CP_COMMIT();
    };

    const int NK = K >> 5;
    fill(0, 0);
    fill(1, 1);

    for (int kc = 0; kc < NK; kc++) {
        const int buf = kc & 1;
        if (kc == NK - 1) { CP_WAIT0(); } else { CP_WAIT1(); }
        __syncthreads();

        const float* sA = smem + buf * BUF_F;
        const float* sB = sA + TILE_F;

        #pragma unroll
        for (int ks = 0; ks < 4; ks++) {
            const int kb = ks * 8 + tig;
            uint32_t af[4][4], bf[4][2];
            #pragma unroll
            for (int mt = 0; mt < 4; mt++) {
                const float* p = sA + (wm * 64 + mt * 16 + g) * PAD + kb;
                af[mt][0] = __float_as_uint(p[0]);
                af[mt][1] = __float_as_uint(p[8 * PAD]);
                af[mt][2] = __float_as_uint(p[4]);
                af[mt][3] = __float_as_uint(p[8 * PAD + 4]);
            }
            #pragma unroll
            for (int nt = 0; nt < 4; nt++) {
                const float* p = sB + (wn * 32 + nt * 8 + g) * PAD + kb;
                bf[nt][0] = __float_as_uint(p[0]);
                bf[nt][1] = __float_as_uint(p[4]);
            }
            #pragma unroll
            for (int mt = 0; mt < 4; mt++)
                #pragma unroll
                for (int nt = 0; nt < 4; nt++)
                    mma_tf32(acc[mt][nt], af[mt], bf[nt]);
        }
        __syncthreads();

        if (kc + 2 < NK) fill(buf, kc + 2);
    }

    #pragma unroll
    for (int mt = 0; mt < 4; mt++) {
        const int row0 = bm + wm * 64 + mt * 16 + g;
        #pragma unroll
        for (int nt = 0; nt < 4; nt++) {
            const int col = bn + wn * 32 + nt * 8 + 2 * tig;
            const float b0 = bias[col], b1 = bias[col + 1];
            float2 o0, o1;
            o0.x = acc[mt][nt][0] + b0;  o0.y = acc[mt][nt][1] + b1;
            o1.x = acc[mt][nt][2] + b0;  o1.y = acc[mt][nt][3] + b1;
            *(float2*)(C + (size_t)row0 * N + col)       = o0;
            *(float2*)(C + (size_t)(row0 + 8) * N + col) = o1;
        }
    }
}

// ===========================================================================
// Tensor-core flash attention, compensated BF16 (m16n8k16).
// CTA: 128 queries x one (b,h); 8 warps, 16 q-rows each. Key tiles of 64.
// Numerics: x = hi_bf16 + lo_bf16, residual ~ eps_bf16^2 ~ 4e-6.
//   QK^T: Qh*Kh + Ql*Kh + Qh*Kl   PV: Ph*Vh + Pl*Vh + Ph*Vl
// 3 bf16 k16 mmas replace 6 tf32 k8 mmas -> half the mma instructions.
// Smem: Q fp32 [128][68] + single raw K/V landing [64][68]x2 + single packed
// hi/lo bf16x2 buffers (K: [key][d-pair], V transposed: [d][key-pair]).
// Total 101KB -> 2 CTAs/SM. Convert pass splits/packs once per CTA per tile.
// S accumulator c-pairs pack directly into PV a-frags (no shuffles).
// ===========================================================================
#define AP        68                            // padded raw row (floats)
#define QT_F      (128 * AP)                    // 8704 floats
#define KVT_F     (64 * AP)                     // 4352 floats
#define A_RAWK    QT_F
#define A_RAWV    (QT_F + KVT_F)
#define PK_W      33                            // packed row stride (words)
#define A_KH      (QT_F + 2 * KVT_F)            // word offsets
#define A_KL      (A_KH + 64 * PK_W)
#define A_VH      (A_KL + 64 * PK_W)
#define A_VL      (A_VH + 64 * PK_W)
#define ATT_SMEM  ((A_VL + 64 * PK_W) * 4)      // 103424 bytes

__global__ __launch_bounds__(256, 2) void attn_mma_kernel(
    const float* __restrict__ qkv, float* __restrict__ ctx)
{
    extern __shared__ float smem[];
    const int tid  = threadIdx.x;
    const int w    = tid >> 5;
    const int lane = tid & 31;
    const int g    = lane >> 2;
    const int tig  = lane & 3;

    const int qt = gridDim.x - 1 - blockIdx.x;     // heaviest tiles first
    const int bh = blockIdx.y;
    const int b  = bh >> 4;
    const int h  = bh & 15;

    const float* base = qkv + (size_t)b * S_LEN * (3 * EMB);
    const int ktmax = 2 * qt + 1;

    // ---- issue Q stage (bundled into first KV group) ----
    {
        const float* Qsrc = base + (size_t)(qt * 128) * (3 * EMB) + h * DH;
        const uint32_t qs = smem_u32(smem);
        #pragma unroll
        for (int i = 0; i < 8; i++) {
            const int id = tid + (i << 8);
            const int r = id >> 4, c4 = id & 15;
            cp_async16(qs + (uint32_t)((r * AP + c4 * 4) * 4),
                       Qsrc + (size_t)r * (3 * EMB) + c4 * 4);
        }
    }

    auto fill_kv = [&](int kt) {
        const float* Ksrc = base + (size_t)(kt * 64) * (3 * EMB) + EMB + h * DH;
        const float* Vsrc = Ksrc + EMB;
        const uint32_t kd = smem_u32(smem + A_RAWK);
        const uint32_t vd = smem_u32(smem + A_RAWV);
        #pragma unroll
        for (int i = 0; i < 4; i++) {
            const int id = tid + (i << 8);
            const int r = id >> 4, c4 = id & 15;
            const uint32_t so = (uint32_t)((r * AP + c4 * 4) * 4);
            const size_t go = (size_t)r * (3 * EMB) + c4 * 4;
            cp_async16(kd + so, Ksrc + go);
            cp_async16(vd + so, Vsrc + go);
        }
        CP_COMMIT();
    };

    fill_kv(0);          // group 0: Q + KV(0)

    uint32_t Qh[4][4], Ql[4][4];
    float S[8][4];
    float O[8][4];
    float m0 = -1e30f, m1 = -1e30f, l0 = 0.0f, l1 = 0.0f;
    #pragma unroll
    for (int nt = 0; nt < 8; nt++)
        #pragma unroll
        for (int i = 0; i < 4; i++)
            O[nt][i] = 0.0f;

    uint32_t* const KH = (uint32_t*)smem + A_KH;
    uint32_t* const KL = (uint32_t*)smem + A_KL;
    uint32_t* const VH = (uint32_t*)smem + A_VH;
    uint32_t* const VL = (uint32_t*)smem + A_VL;

    for (int kt = 0; kt <= ktmax; kt++) {
        CP_WAIT0();
        __syncthreads();   // raw landed AND previous tile's mma done (packed free)

        // ---- convert pass: split+pack K and V once per CTA ----
        {
            const float* rawK = smem + A_RAWK;
            const float* rawV = smem + A_RAWV;
            // K: [64 keys][16 float4 groups] -> KH/KL[key][d-pair]
            #pragma unroll
            for (int i = 0; i < 4; i++) {
                const int id = tid + (i << 8);
                const int r = id >> 4, c4 = id & 15;
                const float4 kx = *(const float4*)(rawK + r * AP + c4 * 4);
                const float h0 = bf16_hi(kx.x), h1 = bf16_hi(kx.y);
                const float h2 = bf16_hi(kx.z), h3 = bf16_hi(kx.w);
                KH[r * PK_W + 2 * c4]     = pack2_bf16(h0, h1);
                KH[r * PK_W + 2 * c4 + 1] = pack2_bf16(h2, h3);
                KL[r * PK_W + 2 * c4]     = pack2_bf16(kx.x - h0, kx.y - h1);
                KL[r * PK_W + 2 * c4 + 1] = pack2_bf16(kx.z - h2, kx.w - h3);
            }
            // V: pairs of key rows -> VH/VL[d][key-pair] (transposed)
            #pragma unroll
            for (int i = 0; i < 2; i++) {
                const int id = tid + (i << 8);
                const int p = id >> 4, c4 = id & 15;
                const float4 v0 = *(const float4*)(rawV + (2 * p) * AP + c4 * 4);
                const float4 v1 = *(const float4*)(rawV + (2 * p + 1) * AP + c4 * 4);
                const float a0 = bf16_hi(v0.x), b0 = bf16_hi(v1.x);
                const float a1 = bf16_hi(v0.y), b1 = bf16_hi(v1.y);
                const float a2 = bf16_hi(v0.z), b2 = bf16_hi(v1.z);
                const float a3 = bf16_hi(v0.w), b3 = bf16_hi(v1.w);
                VH[(4 * c4 + 0) * PK_W + p] = pack2_bf16(a0, b0);
                VH[(4 * c4 + 1) * PK_W + p] = pack2_bf16(a1, b1);
                VH[(4 * c4 + 2) * PK_W + p] = pack2_bf16(a2, b2);
                VH[(4 * c4 + 3) * PK_W + p] = pack2_bf16(a3, b3);
                VL[(4 * c4 + 0) * PK_W + p] = pack2_bf16(v0.x - a0, v1.x - b0);
                VL[(4 * c4 + 1) * PK_W + p] = pack2_bf16(v0.y - a1, v1.y - b1);
                VL[(4 * c4 + 2) * PK_W + p] = pack2_bf16(v0.z - a2, v1.z - b2);
                VL[(4 * c4 + 3) * PK_W + p] = pack2_bf16(v0.w - a3, v1.w - b3);
            }
        }
        __syncthreads();

        if (kt < ktmax) fill_kv(kt + 1);   // raw consumed; prefetch overlaps mma

        if (kt == 0) {   // Q fragments: split fp32 -> bf16 hi/lo, pack pairs
            const float* Qp  = smem + (16 * w + g) * AP;
            const float* Qp8 = Qp + 8 * AP;
            #pragma unroll
            for (int kc = 0; kc < 4; kc++) {
                const float2 q0 = *(const float2*)(Qp  + 16 * kc + 2 * tig);
                const float2 q1 = *(const float2*)(Qp8 + 16 * kc + 2 * tig);
                const float2 q2 = *(const float2*)(Qp  + 16 * kc + 2 * tig + 8);
                const float2 q3 = *(const float2*)(Qp8 + 16 * kc + 2 * tig + 8);
                float ha, hb;
                ha = bf16_hi(q0.x); hb = bf16_hi(q0.y);
                Qh[kc][0] = pack2_bf16(ha, hb);
                Ql[kc][0] = pack2_bf16(q0.x - ha, q0.y - hb);
                ha = bf16_hi(q1.x); hb = bf16_hi(q1.y);
                Qh[kc][1] = pack2_bf16(ha, hb);
                Ql[kc][1] = pack2_bf16(q1.x - ha, q1.y - hb);
                ha = bf16_hi(q2.x); hb = bf16_hi(q2.y);
                Qh[kc][2] = pack2_bf16(ha, hb);
                Ql[kc][2] = pack2_bf16(q2.x - ha, q2.y - hb);
                ha = bf16_hi(q3.x); hb = bf16_hi(q3.y);
                Qh[kc][3] = pack2_bf16(ha, hb);
                Ql[kc][3] = pack2_bf16(q3.x - ha, q3.y - hb);
            }
        }

        // ---- S = Q K^T (compensated bf16) ----
        #pragma unroll
        for (int nt = 0; nt < 8; nt++)
            #pragma unroll
            for (int i = 0; i < 4; i++)
                S[nt][i] = 0.0f;

        #pragma unroll
        for (int kc = 0; kc < 4; kc++) {
            #pragma unroll
            for (int nt = 0; nt < 8; nt++) {
                const uint32_t* kh_ = KH + (nt * 8 + g) * PK_W + kc * 8 + tig;
                const uint32_t* kl_ = KL + (nt * 8 + g) * PK_W + kc * 8 + tig;
                uint32_t bh_[2] = { kh_[0], kh_[4] };
                uint32_t bl_[2] = { kl_[0], kl_[4] };
                mma_bf16(S[nt], Qh[kc], bh_);
                mma_bf16(S[nt], Ql[kc], bh_);
                mma_bf16(S[nt], Qh[kc], bl_);
            }
        }

        // ---- causal mask (diagonal region only) ----
        if (kt >= 2 * qt) {
            const int q0 = 16 * w + g;
            const int q1 = q0 + 8;
            const int kb0 = (kt - 2 * qt) * 64;
            #pragma unroll
            for (int nt = 0; nt < 8; nt++) {
                const int kc = kb0 + nt * 8 + 2 * tig;
                if (kc     > q0) S[nt][0] = -1e30f;
                if (kc + 1 > q0) S[nt][1] = -1e30f;
                if (kc     > q1) S[nt][2] = -1e30f;
                if (kc + 1 > q1) S[nt][3] = -1e30f;
            }
        }

        // ---- online softmax (scale 0.125 folded into exp) ----
        float t0 = -1e30f, t1 = -1e30f;
        #pragma unroll
        for (int nt = 0; nt < 8; nt++) {
            t0 = fmaxf(t0, fmaxf(S[nt][0], S[nt][1]));
            t1 = fmaxf(t1, fmaxf(S[nt][2], S[nt][3]));
        }
        #pragma unroll
        for (int o = 1; o <= 2; o <<= 1) {
            t0 = fmaxf(t0, __shfl_xor_sync(0xffffffffu, t0, o));
            t1 = fmaxf(t1, __shfl_xor_sync(0xffffffffu, t1, o));
        }
        const float mn0 = fmaxf(m0, t0), mn1 = fmaxf(m1, t1);
        const float c0 = __expf(0.125f * (m0 - mn0));
        const float c1 = __expf(0.125f * (m1 - mn1));
        m0 = mn0; m1 = mn1;

        float rs0 = 0.0f, rs1 = 0.0f;
        #pragma unroll
        for (int nt = 0; nt < 8; nt++) {
            S[nt][0] = __expf(0.125f * (S[nt][0] - mn0));
            S[nt][1] = __expf(0.125f * (S[nt][1] - mn0));
            S[nt][2] = __expf(0.125f * (S[nt][2] - mn1));
            S[nt][3] = __expf(0.125f * (S[nt][3] - mn1));
            rs0 += S[nt][0] + S[nt][1];
            rs1 += S[nt][2] + S[nt][3];
        }
        #pragma unroll
        for (int o = 1; o <= 2; o <<= 1) {
            rs0 += __shfl_xor_sync(0xffffffffu, rs0, o);
            rs1 += __shfl_xor_sync(0xffffffffu, rs1, o);
        }
        l0 = l0 * c0 + rs0;
        l1 = l1 * c1 + rs1;

        #pragma unroll
        for (int nt = 0; nt < 8; nt++) {
            O[nt][0] *= c0; O[nt][1] *= c0;
            O[nt][2] *= c1; O[nt][3] *= c1;
        }

        // ---- O += P V (compensated bf16; S c-pairs pack directly) ----
        #pragma unroll
        for (int kc = 0; kc < 4; kc++) {
            uint32_t aPh[4], aPl[4];
            {
                float ha, hb;
                ha = bf16_hi(S[2 * kc][0]); hb = bf16_hi(S[2 * kc][1]);
                aPh[0] = pack2_bf16(ha, hb);
                aPl[0] = pack2_bf16(S[2 * kc][0] - ha, S[2 * kc][1] - hb);
                ha = bf16_hi(S[2 * kc][2]); hb = bf16_hi(S[2 * kc][3]);
                aPh[1] = pack2_bf16(ha, hb);
                aPl[1] = pack2_bf16(S[2 * kc][2] - ha, S[2 * kc][3] - hb);
                ha = bf16_hi(S[2 * kc + 1][0]); hb = bf16_hi(S[2 * kc + 1][1]);
                aPh[2] = pack2_bf16(ha, hb);
                aPl[2] = pack2_bf16(S[2 * kc + 1][0] - ha, S[2 * kc + 1][1] - hb);
                ha = bf16_hi(S[2 * kc + 1][2]); hb = bf16_hi(S[2 * kc + 1][3]);
                aPh[3] = pack2_bf16(ha, hb);
                aPl[3] = pack2_bf16(S[2 * kc + 1][2] - ha, S[2 * kc + 1][3] - hb);
            }
            #pragma unroll
            for (int nt = 0; nt < 8; nt++) {
                const uint32_t* vh_ = VH + (nt * 8 + g) * PK_W + kc * 8 + tig;
                const uint32_t* vl_ = VL + (nt * 8 + g) * PK_W + kc * 8 + tig;
                uint32_t bh_[2] = { vh_[0], vh_[4] };
                uint32_t bl_[2] = { vl_[0], vl_[4] };
                mma_bf16(O[nt], aPh, bh_);
                mma_bf16(O[nt], aPl, bh_);
                mma_bf16(O[nt], aPh, bl_);
            }
        }
        // next iteration's post-wait __syncthreads() protects packed buffers
    }

    // ---- normalize + tf32-round + write ctx (gemm2 reads raw bits) ----
    const float i0 = 1.0f / l0, i1 = 1.0f / l1;
    const size_t row0 = (size_t)b * S_LEN + qt * 128 + 16 * w + g;
    #pragma unroll
    for (int nt = 0; nt < 8; nt++) {
        const int col = h * DH + nt * 8 + 2 * tig;
        float2 o0, o1;
        o0.x = rnd_tf32(O[nt][0] * i0);  o0.y = rnd_tf32(O[nt][1] * i0);
        o1.x = rnd_tf32(O[nt][2] * i1);  o1.y = rnd_tf32(O[nt][3] * i1);
        *(float2*)(ctx + row0 * EMB + col)       = o0;
        *(float2*)(ctx + (row0 + 8) * EMB + col) = o1;
    }
}

// ===========================================================================
// Launch: pre-round -> gemm1 -> attention -> gemm2
// ===========================================================================
extern "C" void kernel_launch(void* const* d_in, const int* in_sizes, int n_in,
                              void* d_out, int out_size)
{
    const float* x     = (const float*)d_in[0];
    const float* w_in  = (const float*)d_in[1];
    const float* b_in  = (const float*)d_in[2];
    const float* w_out = (const float*)d_in[3];
    const float* b_out = (const float*)d_in[4];
    float* out = (float*)d_out;

    float *qkv = nullptr, *ctx = nullptr, *xr = nullptr, *wir = nullptr, *wor = nullptr;
    cudaGetSymbolAddress((void**)&qkv, g_qkv);
    cudaGetSymbolAddress((void**)&ctx, g_ctx);
    cudaGetSymbolAddress((void**)&xr,  g_xr);
    cudaGetSymbolAddress((void**)&wir, g_wir);
    cudaGetSymbolAddress((void**)&wor, g_wor);

    const int M = BATCH * S_LEN;   // 4096

    static bool attr_set = false;
    if (!attr_set) {
        cudaFuncSetAttribute(gemm_mma,
                             cudaFuncAttributeMaxDynamicSharedMemorySize, GM_SMEM);
        cudaFuncSetAttribute(attn_mma_kernel,
                             cudaFuncAttributeMaxDynamicSharedMemorySize, ATT_SMEM);
        attr_set = true;
    }

    // 0) pre-round GEMM operands to tf32 (RNA), once
    {
        const int nx = M * EMB / 4;            // 1048576
        const int nw = 3 * EMB * EMB / 4;      // 786432
        const int no = EMB * EMB / 4;          // 262144
        round_tf32_kernel<<<1184, 256>>>((const float4*)x,     (float4*)xr,  nx);
        round_tf32_kernel<<<1184, 256>>>((const float4*)w_in,  (float4*)wir, nw);
        round_tf32_kernel<<<1184, 256>>>((const float4*)w_out, (float4*)wor, no);
    }

    // 1) qkv = x @ in_proj_w^T + in_proj_b   [4096, 3072]
    gemm_mma<<<dim3((3 * EMB) / 128, M / 128), 256, GM_SMEM>>>(
        xr, wir, b_in, qkv, M, 3 * EMB, EMB);

    // 2) fused causal attention -> ctx [4096, 1024] (tf32-rounded)
    attn_mma_kernel<<<dim3(S_LEN / 128, BATCH * HEADS), 256, ATT_SMEM>>>(qkv, ctx);

    // 3) out = ctx @ out_proj_w^T + out_proj_b   [4096, 1024]
    gemm_mma<<<dim3(EMB / 128, M / 128), 256, GM_SMEM>>>(
        ctx, wor, b_out, out, M, EMB, EMB);
}

// round 9
// speedup vs baseline: 1.0598x; 1.0598x over previous
#include <cuda_runtime.h>
#include <cstdint>

// Problem constants
#define S_LEN 2048
#define EMB   1024
#define HEADS 16
#define DH    64
#define BATCH 2

// Scratch (no allocations allowed)
__device__ float g_qkv[(size_t)BATCH * S_LEN * 3 * EMB];   // [B,S,3E]
__device__ float g_ctx[(size_t)BATCH * S_LEN * EMB];       // [B,S,E] (tf32-rounded)
__device__ float g_xr [(size_t)BATCH * S_LEN * EMB];       // rounded x
__device__ float g_wir[(size_t)3 * EMB * EMB];             // rounded in_proj_w
__device__ float g_wor[(size_t)EMB * EMB];                 // rounded out_proj_w

// ===========================================================================
// Helpers
// ===========================================================================
__device__ __forceinline__ uint32_t smem_u32(const void* p) {
    uint32_t a;
    asm("{ .reg .u64 t; cvta.to.shared.u64 t, %1; cvt.u32.u64 %0, t; }"
        : "=r"(a) : "l"(p));
    return a;
}

__device__ __forceinline__ void cp_async16(uint32_t dst, const void* src) {
    asm volatile("cp.async.cg.shared.global [%0], [%1], 16;"
                 :: "r"(dst), "l"(src));
}
#define CP_COMMIT() asm volatile("cp.async.commit_group;")
#define CP_WAIT1()  asm volatile("cp.async.wait_group 1;")
#define CP_WAIT0()  asm volatile("cp.async.wait_group 0;")

__device__ __forceinline__ uint32_t f2tf32(float f) {
    uint32_t r;
    asm("cvt.rna.tf32.f32 %0, %1;" : "=r"(r) : "f"(f));
    return r;
}
__device__ __forceinline__ float rnd_tf32(float f) {
    return __uint_as_float(f2tf32(f));
}

// bf16 round-to-nearest-even "hi" part of an fp32 (exact bf16 value as fp32)
__device__ __forceinline__ float bf16_hi(float x) {
    uint32_t xb = __float_as_uint(x);
    uint32_t hb = (xb + 0x7fffu + ((xb >> 16) & 1u)) & 0xffff0000u;
    return __uint_as_float(hb);
}
// Pack two fp32 -> bf16x2 register: e0 -> low half (lower k index), e1 -> high
__device__ __forceinline__ uint32_t pack2_bf16(float e0, float e1) {
    uint32_t r;
    asm("cvt.rn.bf16x2.f32 %0, %1, %2;" : "=r"(r) : "f"(e1), "f"(e0));
    return r;
}

// mma.sync m16n8k8 tf32: D += A*B, fp32 accumulate
__device__ __forceinline__ void mma_tf32(
    float* c, const uint32_t* a, const uint32_t* b)
{
    asm volatile(
        "mma.sync.aligned.m16n8k8.row.col.f32.tf32.tf32.f32 "
        "{%0,%1,%2,%3}, {%4,%5,%6,%7}, {%8,%9}, {%0,%1,%2,%3};"
        : "+f"(c[0]), "+f"(c[1]), "+f"(c[2]), "+f"(c[3])
        : "r"(a[0]), "r"(a[1]), "r"(a[2]), "r"(a[3]), "r"(b[0]), "r"(b[1]));
}

// mma.sync m16n8k16 bf16: D += A*B, fp32 accumulate
__device__ __forceinline__ void mma_bf16(
    float* c, const uint32_t* a, const uint32_t* b)
{
    asm volatile(
        "mma.sync.aligned.m16n8k16.row.col.f32.bf16.bf16.f32 "
        "{%0,%1,%2,%3}, {%4,%5,%6,%7}, {%8,%9}, {%0,%1,%2,%3};"
        : "+f"(c[0]), "+f"(c[1]), "+f"(c[2]), "+f"(c[3])
        : "r"(a[0]), "r"(a[1]), "r"(a[2]), "r"(a[3]), "r"(b[0]), "r"(b[1]));
}

// ===========================================================================
// Elementwise tf32 pre-rounding (RNA). Idempotent; feeds GEMMs raw bits.
// ===========================================================================
__global__ __launch_bounds__(256) void round_tf32_kernel(
    const float4* __restrict__ src, float4* __restrict__ dst, int n4)
{
    for (int i = blockIdx.x * 256 + threadIdx.x; i < n4; i += gridDim.x * 256) {
        float4 v = src[i];
        v.x = rnd_tf32(v.x); v.y = rnd_tf32(v.y);
        v.z = rnd_tf32(v.z); v.w = rnd_tf32(v.w);
        dst[i] = v;
    }
}

// ===========================================================================
// tf32 tensor-core GEMM on PRE-ROUNDED inputs (unchanged):
//   C[M,N] = A[M,K] @ B[N,K]^T + bias[N]
// ===========================================================================
#define PAD     36
#define TILE_F  (128 * PAD)
#define BUF_F   (2 * TILE_F)
#define GM_SMEM (2 * BUF_F * 4)

__global__ __launch_bounds__(256, 2) void gemm_mma(
    const float* __restrict__ A, const float* __restrict__ B,
    const float* __restrict__ bias, float* __restrict__ C,
    int M, int N, int K)
{
    extern __shared__ float smem[];
    const int tid  = threadIdx.x;
    const int wid  = tid >> 5;
    const int lane = tid & 31;
    const int wm   = wid >> 2;
    const int wn   = wid & 3;
    const int g    = lane >> 2;
    const int tig  = lane & 3;
    const int bm   = blockIdx.y * 128;
    const int bn   = blockIdx.x * 128;

    float acc[4][4][4];
    #pragma unroll
    for (int mt = 0; mt < 4; mt++)
        #pragma unroll
        for (int nt = 0; nt < 4; nt++)
            #pragma unroll
            for (int i = 0; i < 4; i++)
                acc[mt][nt][i] = 0.0f;

    auto fill = [&](int buf, int kc) {
        const int k0 = kc << 5;
        const uint32_t sA = smem_u32(smem + buf * BUF_F);
        const uint32_t sB = sA + TILE_F * 4;
        #pragma unroll
        for (int i = 0; i < 4; i++) {
            const int id = tid + (i << 8);
            const int r  = id >> 3;
            const int c  = id & 7;
            const uint32_t so = (uint32_t)(r * PAD + c * 4) * 4;
            cp_async16(sA + so, A + (size_t)(bm + r) * K + k0 + c * 4);
            cp_async16(sB + so, B + (size_t)(bn + r) * K + k0 + c * 4);
        }
        CP_COMMIT();
    };

    const int NK = K >> 5;
    fill(0, 0);
    fill(1, 1);

    for (int kc = 0; kc < NK; kc++) {
        const int buf = kc & 1;
        if (kc == NK - 1) { CP_WAIT0(); } else { CP_WAIT1(); }
        __syncthreads();

        const float* sA = smem + buf * BUF_F;
        const float* sB = sA + TILE_F;

        #pragma unroll
        for (int ks = 0; ks < 4; ks++) {
            const int kb = ks * 8 + tig;
            uint32_t af[4][4], bf[4][2];
            #pragma unroll
            for (int mt = 0; mt < 4; mt++) {
                const float* p = sA + (wm * 64 + mt * 16 + g) * PAD + kb;
                af[mt][0] = __float_as_uint(p[0]);
                af[mt][1] = __float_as_uint(p[8 * PAD]);
                af[mt][2] = __float_as_uint(p[4]);
                af[mt][3] = __float_as_uint(p[8 * PAD + 4]);
            }
            #pragma unroll
            for (int nt = 0; nt < 4; nt++) {
                const float* p = sB + (wn * 32 + nt * 8 + g) * PAD + kb;
                bf[nt][0] = __float_as_uint(p[0]);
                bf[nt][1] = __float_as_uint(p[4]);
            }
            #pragma unroll
            for (int mt = 0; mt < 4; mt++)
                #pragma unroll
                for (int nt = 0; nt < 4; nt++)
                    mma_tf32(acc[mt][nt], af[mt], bf[nt]);
        }
        __syncthreads();

        if (kc + 2 < NK) fill(buf, kc + 2);
    }

    #pragma unroll
    for (int mt = 0; mt < 4; mt++) {
        const int row0 = bm + wm * 64 + mt * 16 + g;
        #pragma unroll
        for (int nt = 0; nt < 4; nt++) {
            const int col = bn + wn * 32 + nt * 8 + 2 * tig;
            const float b0 = bias[col], b1 = bias[col + 1];
            float2 o0, o1;
            o0.x = acc[mt][nt][0] + b0;  o0.y = acc[mt][nt][1] + b1;
            o1.x = acc[mt][nt][2] + b0;  o1.y = acc[mt][nt][3] + b1;
            *(float2*)(C + (size_t)row0 * N + col)       = o0;
            *(float2*)(C + (size_t)(row0 + 8) * N + col) = o1;
        }
    }
}

// ===========================================================================
// Tensor-core flash attention, compensated BF16 (m16n8k16).
// IDENTICAL math/layout to round 8; the ONLY change is removing the
// 2-CTA launch-bounds cap that forced <=128 regs and spilled the mainloop.
// 1 CTA/SM, ~150 regs, zero spills: mainloop is pure LDS + mma.
// ===========================================================================
#define AP        68                            // padded raw row (floats)
#define QT_F      (128 * AP)                    // 8704 floats
#define KVT_F     (64 * AP)                     // 4352 floats
#define A_RAWK    QT_F
#define A_RAWV    (QT_F + KVT_F)
#define PK_W      33                            // packed row stride (words)
#define A_KH      (QT_F + 2 * KVT_F)            // word offsets
#define A_KL      (A_KH + 64 * PK_W)
#define A_VH      (A_KL + 64 * PK_W)
#define A_VL      (A_VH + 64 * PK_W)
#define ATT_SMEM  ((A_VL + 64 * PK_W) * 4)      // 103424 bytes

__global__ __launch_bounds__(256) void attn_mma_kernel(
    const float* __restrict__ qkv, float* __restrict__ ctx)
{
    extern __shared__ float smem[];
    const int tid  = threadIdx.x;
    const int w    = tid >> 5;
    const int lane = tid & 31;
    const int g    = lane >> 2;
    const int tig  = lane & 3;

    const int qt = gridDim.x - 1 - blockIdx.x;     // heaviest tiles first
    const int bh = blockIdx.y;
    const int b  = bh >> 4;
    const int h  = bh & 15;

    const float* base = qkv + (size_t)b * S_LEN * (3 * EMB);
    const int ktmax = 2 * qt + 1;

    // ---- issue Q stage (bundled into first KV group) ----
    {
        const float* Qsrc = base + (size_t)(qt * 128) * (3 * EMB) + h * DH;
        const uint32_t qs = smem_u32(smem);
        #pragma unroll
        for (int i = 0; i < 8; i++) {
            const int id = tid + (i << 8);
            const int r = id >> 4, c4 = id & 15;
            cp_async16(qs + (uint32_t)((r * AP + c4 * 4) * 4),
                       Qsrc + (size_t)r * (3 * EMB) + c4 * 4);
        }
    }

    auto fill_kv = [&](int kt) {
        const float* Ksrc = base + (size_t)(kt * 64) * (3 * EMB) + EMB + h * DH;
        const float* Vsrc = Ksrc + EMB;
        const uint32_t kd = smem_u32(smem + A_RAWK);
        const uint32_t vd = smem_u32(smem + A_RAWV);
        #pragma unroll
        for (int i = 0; i < 4; i++) {
            const int id = tid + (i << 8);
            const int r = id >> 4, c4 = id & 15;
            const uint32_t so = (uint32_t)((r * AP + c4 * 4) * 4);
            const size_t go = (size_t)r * (3 * EMB) + c4 * 4;
            cp_async16(kd + so, Ksrc + go);
            cp_async16(vd + so, Vsrc + go);
        }
        CP_COMMIT();
    };

    fill_kv(0);          // group 0: Q + KV(0)

    uint32_t Qh[4][4], Ql[4][4];
    float S[8][4];
    float O[8][4];
    float m0 = -1e30f, m1 = -1e30f, l0 = 0.0f, l1 = 0.0f;
    #pragma unroll
    for (int nt = 0; nt < 8; nt++)
        #pragma unroll
        for (int i = 0; i < 4; i++)
            O[nt][i] = 0.0f;

    uint32_t* const KH = (uint32_t*)smem + A_KH;
    uint32_t* const KL = (uint32_t*)smem + A_KL;
    uint32_t* const VH = (uint32_t*)smem + A_VH;
    uint32_t* const VL = (uint32_t*)smem + A_VL;

    for (int kt = 0; kt <= ktmax; kt++) {
        CP_WAIT0();
        __syncthreads();   // raw landed AND previous tile's mma done (packed free)

        // ---- convert pass: split+pack K and V once per CTA ----
        {
            const float* rawK = smem + A_RAWK;
            const float* rawV = smem + A_RAWV;
            // K: [64 keys][16 float4 groups] -> KH/KL[key][d-pair]
            #pragma unroll
            for (int i = 0; i < 4; i++) {
                const int id = tid + (i << 8);
                const int r = id >> 4, c4 = id & 15;
                const float4 kx = *(const float4*)(rawK + r * AP + c4 * 4);
                const float h0 = bf16_hi(kx.x), h1 = bf16_hi(kx.y);
                const float h2 = bf16_hi(kx.z), h3 = bf16_hi(kx.w);
                KH[r * PK_W + 2 * c4]     = pack2_bf16(h0, h1);
                KH[r * PK_W + 2 * c4 + 1] = pack2_bf16(h2, h3);
                KL[r * PK_W + 2 * c4]     = pack2_bf16(kx.x - h0, kx.y - h1);
                KL[r * PK_W + 2 * c4 + 1] = pack2_bf16(kx.z - h2, kx.w - h3);
            }
            // V: pairs of key rows -> VH/VL[d][key-pair] (transposed)
            #pragma unroll
            for (int i = 0; i < 2; i++) {
                const int id = tid + (i << 8);
                const int p = id >> 4, c4 = id & 15;
                const float4 v0 = *(const float4*)(rawV + (2 * p) * AP + c4 * 4);
                const float4 v1 = *(const float4*)(rawV + (2 * p + 1) * AP + c4 * 4);
                const float a0 = bf16_hi(v0.x), b0 = bf16_hi(v1.x);
                const float a1 = bf16_hi(v0.y), b1 = bf16_hi(v1.y);
                const float a2 = bf16_hi(v0.z), b2 = bf16_hi(v1.z);
                const float a3 = bf16_hi(v0.w), b3 = bf16_hi(v1.w);
                VH[(4 * c4 + 0) * PK_W + p] = pack2_bf16(a0, b0);
                VH[(4 * c4 + 1) * PK_W + p] = pack2_bf16(a1, b1);
                VH[(4 * c4 + 2) * PK_W + p] = pack2_bf16(a2, b2);
                VH[(4 * c4 + 3) * PK_W + p] = pack2_bf16(a3, b3);
                VL[(4 * c4 + 0) * PK_W + p] = pack2_bf16(v0.x - a0, v1.x - b0);
                VL[(4 * c4 + 1) * PK_W + p] = pack2_bf16(v0.y - a1, v1.y - b1);
                VL[(4 * c4 + 2) * PK_W + p] = pack2_bf16(v0.z - a2, v1.z - b2);
                VL[(4 * c4 + 3) * PK_W + p] = pack2_bf16(v0.w - a3, v1.w - b3);
            }
        }
        __syncthreads();

        if (kt < ktmax) fill_kv(kt + 1);   // raw consumed; prefetch overlaps mma

        if (kt == 0) {   // Q fragments: split fp32 -> bf16 hi/lo, pack pairs
            const float* Qp  = smem + (16 * w + g) * AP;
            const float* Qp8 = Qp + 8 * AP;
            #pragma unroll
            for (int kc = 0; kc < 4; kc++) {
                const float2 q0 = *(const float2*)(Qp  + 16 * kc + 2 * tig);
                const float2 q1 = *(const float2*)(Qp8 + 16 * kc + 2 * tig);
                const float2 q2 = *(const float2*)(Qp  + 16 * kc + 2 * tig + 8);
                const float2 q3 = *(const float2*)(Qp8 + 16 * kc + 2 * tig + 8);
                float ha, hb;
                ha = bf16_hi(q0.x); hb = bf16_hi(q0.y);
                Qh[kc][0] = pack2_bf16(ha, hb);
                Ql[kc][0] = pack2_bf16(q0.x - ha, q0.y - hb);
                ha = bf16_hi(q1.x); hb = bf16_hi(q1.y);
                Qh[kc][1] = pack2_bf16(ha, hb);
                Ql[kc][1] = pack2_bf16(q1.x - ha, q1.y - hb);
                ha = bf16_hi(q2.x); hb = bf16_hi(q2.y);
                Qh[kc][2] = pack2_bf16(ha, hb);
                Ql[kc][2] = pack2_bf16(q2.x - ha, q2.y - hb);
                ha = bf16_hi(q3.x); hb = bf16_hi(q3.y);
                Qh[kc][3] = pack2_bf16(ha, hb);
                Ql[kc][3] = pack2_bf16(q3.x - ha, q3.y - hb);
            }
        }

        // ---- S = Q K^T (compensated bf16) ----
        #pragma unroll
        for (int nt = 0; nt < 8; nt++)
            #pragma unroll
            for (int i = 0; i < 4; i++)
                S[nt][i] = 0.0f;

        #pragma unroll
        for (int kc = 0; kc < 4; kc++) {
            #pragma unroll
            for (int nt = 0; nt < 8; nt++) {
                const uint32_t* kh_ = KH + (nt * 8 + g) * PK_W + kc * 8 + tig;
                const uint32_t* kl_ = KL + (nt * 8 + g) * PK_W + kc * 8 + tig;
                uint32_t bh_[2] = { kh_[0], kh_[4] };
                uint32_t bl_[2] = { kl_[0], kl_[4] };
                mma_bf16(S[nt], Qh[kc], bh_);
                mma_bf16(S[nt], Ql[kc], bh_);
                mma_bf16(S[nt], Qh[kc], bl_);
            }
        }

        // ---- causal mask (diagonal region only) ----
        if (kt >= 2 * qt) {
            const int q0 = 16 * w + g;
            const int q1 = q0 + 8;
            const int kb0 = (kt - 2 * qt) * 64;
            #pragma unroll
            for (int nt = 0; nt < 8; nt++) {
                const int kc = kb0 + nt * 8 + 2 * tig;
                if (kc     > q0) S[nt][0] = -1e30f;
                if (kc + 1 > q0) S[nt][1] = -1e30f;
                if (kc     > q1) S[nt][2] = -1e30f;
                if (kc + 1 > q1) S[nt][3] = -1e30f;
            }
        }

        // ---- online softmax (scale 0.125 folded into exp) ----
        float t0 = -1e30f, t1 = -1e30f;
        #pragma unroll
        for (int nt = 0; nt < 8; nt++) {
            t0 = fmaxf(t0, fmaxf(S[nt][0], S[nt][1]));
            t1 = fmaxf(t1, fmaxf(S[nt][2], S[nt][3]));
        }
        #pragma unroll
        for (int o = 1; o <= 2; o <<= 1) {
            t0 = fmaxf(t0, __shfl_xor_sync(0xffffffffu, t0, o));
            t1 = fmaxf(t1, __shfl_xor_sync(0xffffffffu, t1, o));
        }
        const float mn0 = fmaxf(m0, t0), mn1 = fmaxf(m1, t1);
        const float c0 = __expf(0.125f * (m0 - mn0));
        const float c1 = __expf(0.125f * (m1 - mn1));
        m0 = mn0; m1 = mn1;

        float rs0 = 0.0f, rs1 = 0.0f;
        #pragma unroll
        for (int nt = 0; nt < 8; nt++) {
            S[nt][0] = __expf(0.125f * (S[nt][0] - mn0));
            S[nt][1] = __expf(0.125f * (S[nt][1] - mn0));
            S[nt][2] = __expf(0.125f * (S[nt][2] - mn1));
            S[nt][3] = __expf(0.125f * (S[nt][3] - mn1));
            rs0 += S[nt][0] + S[nt][1];
            rs1 += S[nt][2] + S[nt][3];
        }
        #pragma unroll
        for (int o = 1; o <= 2; o <<= 1) {
            rs0 += __shfl_xor_sync(0xffffffffu, rs0, o);
            rs1 += __shfl_xor_sync(0xffffffffu, rs1, o);
        }
        l0 = l0 * c0 + rs0;
        l1 = l1 * c1 + rs1;

        #pragma unroll
        for (int nt = 0; nt < 8; nt++) {
            O[nt][0] *= c0; O[nt][1] *= c0;
            O[nt][2] *= c1; O[nt][3] *= c1;
        }

        // ---- O += P V (compensated bf16; S c-pairs pack directly) ----
        #pragma unroll
        for (int kc = 0; kc < 4; kc++) {
            uint32_t aPh[4], aPl[4];
            {
                float ha, hb;
                ha = bf16_hi(S[2 * kc][0]); hb = bf16_hi(S[2 * kc][1]);
                aPh[0] = pack2_bf16(ha, hb);
                aPl[0] = pack2_bf16(S[2 * kc][0] - ha, S[2 * kc][1] - hb);
                ha = bf16_hi(S[2 * kc][2]); hb = bf16_hi(S[2 * kc][3]);
                aPh[1] = pack2_bf16(ha, hb);
                aPl[1] = pack2_bf16(S[2 * kc][2] - ha, S[2 * kc][3] - hb);
                ha = bf16_hi(S[2 * kc + 1][0]); hb = bf16_hi(S[2 * kc + 1][1]);
                aPh[2] = pack2_bf16(ha, hb);
                aPl[2] = pack2_bf16(S[2 * kc + 1][0] - ha, S[2 * kc + 1][1] - hb);
                ha = bf16_hi(S[2 * kc + 1][2]); hb = bf16_hi(S[2 * kc + 1][3]);
                aPh[3] = pack2_bf16(ha, hb);
                aPl[3] = pack2_bf16(S[2 * kc + 1][2] - ha, S[2 * kc + 1][3] - hb);
            }
            #pragma unroll
            for (int nt = 0; nt < 8; nt++) {
                const uint32_t* vh_ = VH + (nt * 8 + g) * PK_W + kc * 8 + tig;
                const uint32_t* vl_ = VL + (nt * 8 + g) * PK_W + kc * 8 + tig;
                uint32_t bh_[2] = { vh_[0], vh_[4] };
                uint32_t bl_[2] = { vl_[0], vl_[4] };
                mma_bf16(O[nt], aPh, bh_);
                mma_bf16(O[nt], aPl, bh_);
                mma_bf16(O[nt], aPh, bl_);
            }
        }
        // next iteration's post-wait __syncthreads() protects packed buffers
    }

    // ---- normalize + tf32-round + write ctx (gemm2 reads raw bits) ----
    const float i0 = 1.0f / l0, i1 = 1.0f / l1;
    const size_t row0 = (size_t)b * S_LEN + qt * 128 + 16 * w + g;
    #pragma unroll
    for (int nt = 0; nt < 8; nt++) {
        const int col = h * DH + nt * 8 + 2 * tig;
        float2 o0, o1;
        o0.x = rnd_tf32(O[nt][0] * i0);  o0.y = rnd_tf32(O[nt][1] * i0);
        o1.x = rnd_tf32(O[nt][2] * i1);  o1.y = rnd_tf32(O[nt][3] * i1);
        *(float2*)(ctx + row0 * EMB + col)       = o0;
        *(float2*)(ctx + (row0 + 8) * EMB + col) = o1;
    }
}

// ===========================================================================
// Launch: pre-round -> gemm1 -> attention -> gemm2
// ===========================================================================
extern "C" void kernel_launch(void* const* d_in, const int* in_sizes, int n_in,
                              void* d_out, int out_size)
{
    const float* x     = (const float*)d_in[0];
    const float* w_in  = (const float*)d_in[1];
    const float* b_in  = (const float*)d_in[2];
    const float* w_out = (const float*)d_in[3];
    const float* b_out = (const float*)d_in[4];
    float* out = (float*)d_out;

    float *qkv = nullptr, *ctx = nullptr, *xr = nullptr, *wir = nullptr, *wor = nullptr;
    cudaGetSymbolAddress((void**)&qkv, g_qkv);
    cudaGetSymbolAddress((void**)&ctx, g_ctx);
    cudaGetSymbolAddress((void**)&xr,  g_xr);
    cudaGetSymbolAddress((void**)&wir, g_wir);
    cudaGetSymbolAddress((void**)&wor, g_wor);

    const int M = BATCH * S_LEN;   // 4096

    static bool attr_set = false;
    if (!attr_set) {
        cudaFuncSetAttribute(gemm_mma,
                             cudaFuncAttributeMaxDynamicSharedMemorySize, GM_SMEM);
        cudaFuncSetAttribute(attn_mma_kernel,
                             cudaFuncAttributeMaxDynamicSharedMemorySize, ATT_SMEM);
        attr_set = true;
    }

    // 0) pre-round GEMM operands to tf32 (RNA), once
    {
        const int nx = M * EMB / 4;            // 1048576
        const int nw = 3 * EMB * EMB / 4;      // 786432
        const int no = EMB * EMB / 4;          // 262144
        round_tf32_kernel<<<1184, 256>>>((const float4*)x,     (float4*)xr,  nx);
        round_tf32_kernel<<<1184, 256>>>((const float4*)w_in,  (float4*)wir, nw);
        round_tf32_kernel<<<1184, 256>>>((const float4*)w_out, (float4*)wor, no);
    }

    // 1) qkv = x @ in_proj_w^T + in_proj_b   [4096, 3072]
    gemm_mma<<<dim3((3 * EMB) / 128, M / 128), 256, GM_SMEM>>>(
        xr, wir, b_in, qkv, M, 3 * EMB, EMB);

    // 2) fused causal attention -> ctx [4096, 1024] (tf32-rounded)
    attn_mma_kernel<<<dim3(S_LEN / 128, BATCH * HEADS), 256, ATT_SMEM>>>(qkv, ctx);

    // 3) out = ctx @ out_proj_w^T + out_proj_b   [4096, 1024]
    gemm_mma<<<dim3(EMB / 128, M / 128), 256, GM_SMEM>>>(
        ctx, wor, b_out, out, M, EMB, EMB);
}